// round 11
// baseline (speedup 1.0000x reference)
#include <cuda_runtime.h>

// ProteinCRF: batched linear-chain CRF NLL.  B=2048, L=2048, T=8.
// out: scalar f32 = mean(denom - num)
//
// R11: split the work by its nature.
//  AUX kernel (parallel, 1 warp/batch, high occupancy): reads int64 tags once,
//    emits per batch: len, tag-only numerator part (start+trans+end), and
//    nibble-packed tags (4b/step). ~40MB traffic, ~8us.
//  SCAN kernel (serial recurrence, 4 lanes/batch, 2 states/lane, 64 blocks x
//    128 thr): ONLY the beta recurrence + a ~5-instr em-path accumulate.
//    No tag loads, no LDS, no length search, no buffer-copy MOVs (ping-pong),
//    renorm every 8 steps, act = one unsigned compare.
//  All lanes run to warp-max length (converged full-mask shuffles, R7 lesson).
//  Deterministic last-block-arrives mean; counter reset for graph replay.

#define CRF_B 2048
#define CRF_L 2048
#define CRF_T 8
#define SCAN_BLOCKS  64
#define SCAN_THREADS 128     // 32 batches/block, 4 lanes/batch

__device__ float        g_llh[CRF_B];
__device__ float        g_numpart[CRF_B];
__device__ int          g_len[CRF_B];
__device__ unsigned     g_ptags[CRF_B * (CRF_L / 8)];   // 8 tags per word
__device__ unsigned int g_count = 0;

// ===================== AUX: tags -> len, numpart, packed ====================
__global__ __launch_bounds__(256)
void crf_aux_kernel(const int* __restrict__ tagsw,
                    const float* __restrict__ transitions,
                    const float* __restrict__ start_tr,
                    const float* __restrict__ end_tr)
{
    __shared__ float s_trans[64];
    __shared__ float s_start[8];
    __shared__ float s_end[8];
    const int tid  = threadIdx.x;
    const int lane = tid & 31;
    if (tid < 64) s_trans[tid] = transitions[tid];
    if (tid < 8)  { s_start[tid] = start_tr[tid]; s_end[tid] = end_tr[tid]; }
    __syncthreads();

    const int tstride = (tagsw[1] == 0) ? 2 : 1;   // int64 vs int32 tags
    const int batch   = blockIdx.x * 8 + (tid >> 5);
    const int* tg     = tagsw + (size_t)batch * CRF_L * tstride;

    float s   = 0.0f;
    int   cnt = 0;
#pragma unroll 4
    for (int i = 0; i < CRF_L / 32; i++) {
        const int t   = i * 32 + lane;
        const int tag = tg[t * tstride];
        cnt += __popc(__ballot_sync(0xFFFFFFFFu, tag != 0));

        int pt = __shfl_up_sync(0xFFFFFFFFu, tag, 1);
        if (lane == 0) pt = (i > 0) ? tg[(t - 1) * tstride] : 0;

        if (tag != 0)
            s += (t == 0) ? s_start[tag - 1]
                          : s_trans[(pt - 1) * 8 + (tag - 1)];

        unsigned v = (unsigned)(tag & 15) << (4 * (lane & 7));
        v |= __shfl_xor_sync(0xFFFFFFFFu, v, 1);
        v |= __shfl_xor_sync(0xFFFFFFFFu, v, 2);
        v |= __shfl_xor_sync(0xFFFFFFFFu, v, 4);
        if ((lane & 7) == 0)
            g_ptags[batch * (CRF_L / 8) + i * 4 + (lane >> 3)] = v;
    }
    // deterministic butterfly reduce of s (cnt already uniform)
#pragma unroll
    for (int off = 16; off > 0; off >>= 1)
        s += __shfl_xor_sync(0xFFFFFFFFu, s, off);
    if (lane == 0) {
        const int last = tg[(cnt - 1) * tstride] - 1;
        g_numpart[batch] = s + s_end[last];
        g_len[batch]     = cnt;
    }
}

// ===================== SCAN: exp-domain forward recurrence ==================
// One 8-step chunk. EM = emission regs, W = packed tag word, T0 = chunk base.
// act = (unsigned)(T0+k-1) < lenu  covers both t>0 and t<len.
#define CRF_CHUNK(EM, W, T0)                                                  \
    _Pragma("unroll")                                                         \
    for (int k = 0; k < 8; k++) {                                             \
        const bool act = (unsigned)((T0) + k - 1) < lenu;                     \
        const int  cur = (int)(((W) >> (4 * k)) & 15u) - 1;                   \
        float ex0 = __expf(EM[k].x), ex1 = __expf(EM[k].y);                   \
        float r10 = __shfl_xor_sync(0xFFFFFFFFu, b0, 1);                      \
        float r11 = __shfl_xor_sync(0xFFFFFFFFu, b1, 1);                      \
        float r20 = __shfl_xor_sync(0xFFFFFFFFu, b0, 2);                      \
        float r21 = __shfl_xor_sync(0xFFFFFFFFu, b1, 2);                      \
        float r30 = __shfl_xor_sync(0xFFFFFFFFu, b0, 3);                      \
        float r31 = __shfl_xor_sync(0xFFFFFFFFu, b1, 3);                      \
        float dA0 = b0  * En[0][0], dA1 = b0  * En[0][1];                     \
        float dB0 = b1  * En[1][0], dB1 = b1  * En[1][1];                     \
        dA0 = fmaf(r10, En[2][0], dA0); dA1 = fmaf(r10, En[2][1], dA1);       \
        dB0 = fmaf(r11, En[3][0], dB0); dB1 = fmaf(r11, En[3][1], dB1);       \
        dA0 = fmaf(r20, En[4][0], dA0); dA1 = fmaf(r20, En[4][1], dA1);       \
        dB0 = fmaf(r21, En[5][0], dB0); dB1 = fmaf(r21, En[5][1], dB1);       \
        dA0 = fmaf(r30, En[6][0], dA0); dA1 = fmaf(r30, En[6][1], dA1);       \
        dB0 = fmaf(r31, En[7][0], dB0); dB1 = fmaf(r31, En[7][1], dB1);       \
        float u0 = (dA0 + dB0) * ex0;                                         \
        float u1 = (dA1 + dB1) * ex1;                                         \
        if (k == 7) {  /* renorm once per chunk; range safe (<2^97) */        \
            float m = fmaxf(fmaxf(fmaxf(b0, b1), fmaxf(r10, r11)),            \
                            fmaxf(fmaxf(r20, r21), fmaxf(r30, r31)));         \
            int e = ((__float_as_int(m) >> 23) & 0xFF) - 127;                 \
            float sc = __int_as_float((127 - e) << 23);                       \
            u0 *= sc; u1 *= sc;                                               \
            eacc += act ? e : 0;                                              \
        }                                                                     \
        float es   = (cur & 1) ? EM[k].y : EM[k].x;                           \
        bool  mine = ((cur >> 1) == g);                                       \
        emsum += (act && mine) ? es : 0.0f;                                   \
        b0 = act ? u0 : b0;                                                   \
        b1 = act ? u1 : b1;                                                   \
    }

__global__ __launch_bounds__(SCAN_THREADS, 1)
void crf_scan_kernel(const float* __restrict__ emissions,
                     const float* __restrict__ transitions,
                     const float* __restrict__ start_tr,
                     const float* __restrict__ end_tr,
                     float*       __restrict__ out)
{
    __shared__ float  s_trans[64];
    __shared__ float  s_start[8];
    __shared__ float  s_end[8];
    __shared__ double s_red[4];
    __shared__ bool   s_last;

    const int tid  = threadIdx.x;
    const int lane = tid & 31;
    if (tid < 64) s_trans[tid] = transitions[tid];
    if (tid < 8)  { s_start[tid] = start_tr[tid]; s_end[tid] = end_tr[tid]; }
    __syncthreads();

    const int g     = tid & 3;
    const int batch = blockIdx.x * 32 + (tid >> 2);

    const float2*   em2  = (const float2*)(emissions + (size_t)batch * (CRF_L * CRF_T));
    const unsigned* ptag = g_ptags + batch * (CRF_L / 8);

    const int len  = g_len[batch];
    const unsigned lenu = (unsigned)(len - 1);
    int lenw = len;
#pragma unroll
    for (int off = 16; off > 0; off >>= 1)
        lenw = max(lenw, __shfl_xor_sync(0xFFFFFFFFu, lenw, off));

    // E rows in per-lane gather order: src pairs 2(g^m), outputs = my 2 cols
    float En[8][2];
#pragma unroll
    for (int m = 0; m < 4; m++) {
        int src = 2 * (g ^ m);
#pragma unroll
        for (int c = 0; c < 2; c++) {
            En[2 * m + 0][c] = __expf(s_trans[(src + 0) * 8 + 2 * g + c]);
            En[2 * m + 1][c] = __expf(s_trans[(src + 1) * 8 + 2 * g + c]);
        }
    }

    // prime chunk A: rows 0..7, word 0
    float2 emA[8], emB[8];
#pragma unroll
    for (int k = 0; k < 8; k++) emA[k] = em2[k * 4 + g];
    unsigned wA = ptag[0], wB;

    // ---- t = 0 init (chunk A step k=0 is act=false) ----
    float2 e0 = emA[0];
    float a0 = s_start[2 * g + 0] + e0.x;
    float a1 = s_start[2 * g + 1] + e0.y;
    float mloc = fmaxf(a0, a1);
    mloc = fmaxf(mloc, __shfl_xor_sync(0xFFFFFFFFu, mloc, 1));
    mloc = fmaxf(mloc, __shfl_xor_sync(0xFFFFFFFFu, mloc, 2));
    const float m0 = mloc;
    float b0 = __expf(a0 - m0), b1 = __expf(a1 - m0);
    int   eacc = 0;

    // em-path contribution at t=0
    float emsum;
    {
        int cur0 = (int)(wA & 15u) - 1;
        emsum = ((cur0 >> 1) == g) ? ((cur0 & 1) ? e0.y : e0.x) : 0.0f;
    }

    // ---- main scan: ping-pong chunks of 8, 16 steps per outer iter ---------
    for (int t0 = 0; t0 < lenw; t0 += 16) {
        const int c = t0 >> 3;
        // prefetch B (rows t0+8..t0+15)
#pragma unroll
        for (int k = 0; k < 8; k++) {
            int tt = min(t0 + 8 + k, CRF_L - 1);
            emB[k] = em2[tt * 4 + g];
        }
        wB = ptag[min(c + 1, CRF_L / 8 - 1)];

        CRF_CHUNK(emA, wA, t0)

        // prefetch A (rows t0+16..t0+23)
#pragma unroll
        for (int k = 0; k < 8; k++) {
            int tt = min(t0 + 16 + k, CRF_L - 1);
            emA[k] = em2[tt * 4 + g];
        }
        wA = ptag[min(c + 2, CRF_L / 8 - 1)];

        CRF_CHUNK(emB, wB, (t0 + 8))
    }

    // ---- finish ------------------------------------------------------------
    emsum += __shfl_xor_sync(0xFFFFFFFFu, emsum, 1);
    emsum += __shfl_xor_sync(0xFFFFFFFFu, emsum, 2);

    float w = b0 * __expf(s_end[2 * g + 0]) + b1 * __expf(s_end[2 * g + 1]);
    w += __shfl_xor_sync(0xFFFFFFFFu, w, 1);
    w += __shfl_xor_sync(0xFFFFFFFFu, w, 2);

    float denom = m0 + (float)eacc * 0.693147180559945309f + __logf(w);

    if (g == 0) g_llh[batch] = denom - (g_numpart[batch] + emsum);

    // ---- last-block-arrives final mean (deterministic) ---------------------
    __threadfence();
    __syncthreads();
    if (tid == 0) {
        unsigned old = atomicAdd(&g_count, 1u);
        s_last = (old == (unsigned)(SCAN_BLOCKS - 1));
    }
    __syncthreads();

    if (s_last) {
        double s = 0.0;
        for (int i = tid; i < CRF_B; i += SCAN_THREADS) s += (double)__ldcg(&g_llh[i]);
#pragma unroll
        for (int off = 16; off > 0; off >>= 1)
            s += __shfl_xor_sync(0xFFFFFFFFu, s, off);
        if (lane == 0) s_red[tid >> 5] = s;
        __syncthreads();
        if (tid == 0) {
            out[0] = (float)((s_red[0] + s_red[1] + s_red[2] + s_red[3])
                             / (double)CRF_B);
            g_count = 0;   // reset for graph replay
        }
    }
}

extern "C" void kernel_launch(void* const* d_in, const int* in_sizes, int n_in,
                              void* d_out, int out_size)
{
    const float* emissions   = (const float*)d_in[0];
    const float* transitions = (const float*)d_in[1];
    const float* start_tr    = (const float*)d_in[2];
    const float* end_tr      = (const float*)d_in[3];
    const int*   tagsw       = (const int*)d_in[4];

    crf_aux_kernel<<<CRF_B / 8, 256>>>(tagsw, transitions, start_tr, end_tr);
    crf_scan_kernel<<<SCAN_BLOCKS, SCAN_THREADS>>>(
        emissions, transitions, start_tr, end_tr, (float*)d_out);
}

// round 12
// speedup vs baseline: 1.0028x; 1.0028x over previous
#include <cuda_runtime.h>

// ProteinCRF: batched linear-chain CRF NLL.  B=2048, L=2048, T=8.
// out: scalar f32 = mean(denom - num)
//
// R12 = R5 mapping (8 lanes/batch, best measured cyc/step) + R11 freight
// eviction + shuffle-free aux.
//  AUX (1 batch/block x 2048 blocks, 256 thr): each thread owns 8 consecutive
//    tags (int4 loads), locally packs nibbles + accumulates start/trans/end
//    path score + count; block reduce. No shuffles in the loop. ~33.5MB.
//  SCAN (8 lanes/batch, 4 batches/warp, 128 blocks x 128 thr): per step only
//    7 shfl + 8 FMA + 1 exp + 3-instr em-path + sel + renorm/8 + prefetch.
//    E in per-lane xor-gather order. Tags only as one packed word / 8 steps.
//  All lanes run to warp-max length (converged full-mask shuffles).
//  Deterministic last-block-arrives mean; counter reset for graph replay.

#define CRF_B 2048
#define CRF_L 2048
#define CRF_T 8
#define SCAN_BLOCKS  128
#define SCAN_THREADS 128     // 16 batches/block, 8 lanes/batch

__device__ float        g_llh[CRF_B];
__device__ float        g_numpart[CRF_B];
__device__ int          g_len[CRF_B];
__device__ unsigned     g_ptags[CRF_B * (CRF_L / 8)];   // 8 tags per word
__device__ unsigned int g_count = 0;

// ===================== AUX: tags -> len, numpart, packed ====================
// One batch per block; thread t owns tags [8t, 8t+8). No shuffles.
__global__ __launch_bounds__(256)
void crf_aux_kernel(const int* __restrict__ tagsw,
                    const float* __restrict__ transitions,
                    const float* __restrict__ start_tr,
                    const float* __restrict__ end_tr)
{
    __shared__ float  s_trans[64];
    __shared__ float  s_start[8];
    __shared__ float  s_end[8];
    __shared__ float  s_sum[8];
    __shared__ int    s_cnt[8];

    const int tid  = threadIdx.x;
    const int lane = tid & 31;
    const int wid  = tid >> 5;
    if (tid < 64) s_trans[tid] = transitions[tid];
    if (tid < 8)  { s_start[tid] = start_tr[tid]; s_end[tid] = end_tr[tid]; }
    __syncthreads();

    const int tstride = (tagsw[1] == 0) ? 2 : 1;   // int64 vs int32 tags
    const int batch   = blockIdx.x;
    const int* tg     = tagsw + (size_t)batch * CRF_L * tstride;

    int lt[8];
    if (tstride == 2) {
        const int4* p = (const int4*)(tg + tid * 16);
        int4 a = p[0], b = p[1], c = p[2], d = p[3];
        lt[0] = a.x; lt[1] = a.z; lt[2] = b.x; lt[3] = b.z;
        lt[4] = c.x; lt[5] = c.z; lt[6] = d.x; lt[7] = d.z;
    } else {
        const int4* p = (const int4*)(tg + tid * 8);
        int4 a = p[0], b = p[1];
        lt[0] = a.x; lt[1] = a.y; lt[2] = a.z; lt[3] = a.w;
        lt[4] = b.x; lt[5] = b.y; lt[6] = b.z; lt[7] = b.w;
    }

    // pack nibbles
    unsigned w = 0;
#pragma unroll
    for (int i = 0; i < 8; i++) w |= (unsigned)(lt[i] & 15) << (4 * i);
    g_ptags[batch * (CRF_L / 8) + tid] = w;

    // local path score + count
    int prev = (tid == 0) ? 0 : tg[(tid * 8 - 1) * tstride];
    float s  = 0.0f;
    int  cnt = 0;
#pragma unroll
    for (int i = 0; i < 8; i++) {
        if (lt[i] != 0) {
            cnt++;
            s += (tid == 0 && i == 0) ? s_start[lt[0] - 1]
                                      : s_trans[(prev - 1) * 8 + (lt[i] - 1)];
        }
        prev = lt[i];
    }

    // reduce (deterministic: butterfly + fixed-order smem sum)
#pragma unroll
    for (int off = 16; off > 0; off >>= 1) {
        s   += __shfl_xor_sync(0xFFFFFFFFu, s, off);
        cnt += __shfl_xor_sync(0xFFFFFFFFu, cnt, off);
    }
    if (lane == 0) { s_sum[wid] = s; s_cnt[wid] = cnt; }
    __syncthreads();
    if (tid == 0) {
        float tot = 0.0f; int len = 0;
#pragma unroll
        for (int i = 0; i < 8; i++) { tot += s_sum[i]; len += s_cnt[i]; }
        const int last = tg[(len - 1) * tstride] - 1;
        g_numpart[batch] = tot + s_end[last];
        g_len[batch]     = len;
    }
}

// ===================== SCAN: exp-domain forward recurrence ==================
// One 8-step chunk. EM = emission regs, W = packed tag word, T0 = chunk base.
#define CRF_CHUNK(EM, W, T0)                                                  \
    _Pragma("unroll")                                                         \
    for (int k = 0; k < 8; k++) {                                             \
        const bool act = (unsigned)((T0) + k - 1) < lenu;                     \
        float ex = __expf(EM[k]);                                             \
        float r1 = __shfl_xor_sync(0xFFFFFFFFu, beta, 1, 8);                  \
        float r2 = __shfl_xor_sync(0xFFFFFFFFu, beta, 2, 8);                  \
        float r3 = __shfl_xor_sync(0xFFFFFFFFu, beta, 3, 8);                  \
        float r4 = __shfl_xor_sync(0xFFFFFFFFu, beta, 4, 8);                  \
        float r5 = __shfl_xor_sync(0xFFFFFFFFu, beta, 5, 8);                  \
        float r6 = __shfl_xor_sync(0xFFFFFFFFu, beta, 6, 8);                  \
        float r7 = __shfl_xor_sync(0xFFFFFFFFu, beta, 7, 8);                  \
        float sA = beta * Eg[0];                                              \
        float sB = r1   * Eg[1];                                              \
        sA = fmaf(r2, Eg[2], sA);                                             \
        sB = fmaf(r3, Eg[3], sB);                                             \
        sA = fmaf(r4, Eg[4], sA);                                             \
        sB = fmaf(r5, Eg[5], sB);                                             \
        sA = fmaf(r6, Eg[6], sA);                                             \
        sB = fmaf(r7, Eg[7], sB);                                             \
        float u = (sA + sB) * ex;                                             \
        if (k == 7) {  /* renorm once per chunk; range safe (<2^100) */       \
            float m = fmaxf(fmaxf(fmaxf(beta, r1), fmaxf(r2, r3)),            \
                            fmaxf(fmaxf(r4, r5), fmaxf(r6, r7)));             \
            int e = ((__float_as_int(m) >> 23) & 0xFF) - 127;                 \
            float sc = __int_as_float((127 - e) << 23);                       \
            u *= sc;                                                          \
            eacc += act ? e : 0;                                              \
        }                                                                     \
        bool mine = (((W) >> (4 * k)) & 15u) == jp1;                          \
        emsum += (act && mine) ? EM[k] : 0.0f;                                \
        beta = act ? u : beta;                                                \
    }

__global__ __launch_bounds__(SCAN_THREADS, 1)
void crf_scan_kernel(const float* __restrict__ emissions,
                     const float* __restrict__ transitions,
                     const float* __restrict__ start_tr,
                     const float* __restrict__ end_tr,
                     float*       __restrict__ out)
{
    __shared__ float  s_trans[64];
    __shared__ float  s_start[8];
    __shared__ float  s_end[8];
    __shared__ double s_red[4];
    __shared__ bool   s_last;

    const int tid  = threadIdx.x;
    const int lane = tid & 31;
    if (tid < 64) s_trans[tid] = transitions[tid];
    if (tid < 8)  { s_start[tid] = start_tr[tid]; s_end[tid] = end_tr[tid]; }
    __syncthreads();

    const int      j     = tid & 7;             // my state
    const unsigned jp1   = (unsigned)(j + 1);   // my tag value
    const int      batch = blockIdx.x * 16 + (tid >> 3);

    const float*    em_base = emissions + (size_t)batch * (CRF_L * CRF_T);
    const unsigned* ptagp   = g_ptags + batch * (CRF_L / 8);

    const int len  = g_len[batch];
    const unsigned lenu = (unsigned)(len - 1);
    int lenw = len;
#pragma unroll
    for (int off = 16; off > 0; off >>= 1)
        lenw = max(lenw, __shfl_xor_sync(0xFFFFFFFFu, lenw, off));

    // E in per-lane xor-gather order: Eg[m] = exp(trans[j^m][j])
    float Eg[8];
#pragma unroll
    for (int m = 0; m < 8; m++) Eg[m] = __expf(s_trans[(j ^ m) * 8 + j]);

    // prime chunk A: rows 0..7, word 0
    float emA[8], emB[8];
#pragma unroll
    for (int k = 0; k < 8; k++) emA[k] = em_base[k * CRF_T + j];
    unsigned wA = ptagp[0], wB;

    // ---- t = 0 init (chunk step k=0 has act=false) ----
    float a0 = s_start[j] + emA[0];
    float mx = a0;
    mx = fmaxf(mx, __shfl_xor_sync(0xFFFFFFFFu, mx, 1, 8));
    mx = fmaxf(mx, __shfl_xor_sync(0xFFFFFFFFu, mx, 2, 8));
    mx = fmaxf(mx, __shfl_xor_sync(0xFFFFFFFFu, mx, 4, 8));
    const float m0 = mx;
    float beta = __expf(a0 - m0);
    int   eacc = 0;
    float emsum = ((wA & 15u) == jp1) ? emA[0] : 0.0f;

    // ---- main scan: ping-pong chunks of 8, 16 steps per outer iter ---------
    for (int t0 = 0; t0 < lenw; t0 += 16) {
        const int c = t0 >> 3;
#pragma unroll
        for (int k = 0; k < 8; k++) {
            int tt = min(t0 + 8 + k, CRF_L - 1);
            emB[k] = em_base[tt * CRF_T + j];
        }
        wB = ptagp[min(c + 1, CRF_L / 8 - 1)];

        CRF_CHUNK(emA, wA, t0)

#pragma unroll
        for (int k = 0; k < 8; k++) {
            int tt = min(t0 + 16 + k, CRF_L - 1);
            emA[k] = em_base[tt * CRF_T + j];
        }
        wA = ptagp[min(c + 2, CRF_L / 8 - 1)];

        CRF_CHUNK(emB, wB, (t0 + 8))
    }

    // ---- finish ------------------------------------------------------------
    emsum += __shfl_xor_sync(0xFFFFFFFFu, emsum, 1, 8);
    emsum += __shfl_xor_sync(0xFFFFFFFFu, emsum, 2, 8);
    emsum += __shfl_xor_sync(0xFFFFFFFFu, emsum, 4, 8);

    float w = beta * __expf(s_end[j]);
    w += __shfl_xor_sync(0xFFFFFFFFu, w, 1, 8);
    w += __shfl_xor_sync(0xFFFFFFFFu, w, 2, 8);
    w += __shfl_xor_sync(0xFFFFFFFFu, w, 4, 8);

    float denom = m0 + (float)eacc * 0.693147180559945309f + __logf(w);

    if (j == 0) g_llh[batch] = denom - (g_numpart[batch] + emsum);

    // ---- last-block-arrives final mean (deterministic) ---------------------
    __threadfence();
    __syncthreads();
    if (tid == 0) {
        unsigned old = atomicAdd(&g_count, 1u);
        s_last = (old == (unsigned)(SCAN_BLOCKS - 1));
    }
    __syncthreads();

    if (s_last) {
        double s = 0.0;
        for (int i = tid; i < CRF_B; i += SCAN_THREADS) s += (double)__ldcg(&g_llh[i]);
#pragma unroll
        for (int off = 16; off > 0; off >>= 1)
            s += __shfl_xor_sync(0xFFFFFFFFu, s, off);
        if (lane == 0) s_red[tid >> 5] = s;
        __syncthreads();
        if (tid == 0) {
            out[0] = (float)((s_red[0] + s_red[1] + s_red[2] + s_red[3])
                             / (double)CRF_B);
            g_count = 0;   // reset for graph replay
        }
    }
}

extern "C" void kernel_launch(void* const* d_in, const int* in_sizes, int n_in,
                              void* d_out, int out_size)
{
    const float* emissions   = (const float*)d_in[0];
    const float* transitions = (const float*)d_in[1];
    const float* start_tr    = (const float*)d_in[2];
    const float* end_tr      = (const float*)d_in[3];
    const int*   tagsw       = (const int*)d_in[4];

    crf_aux_kernel<<<CRF_B, 256>>>(tagsw, transitions, start_tr, end_tr);
    crf_scan_kernel<<<SCAN_BLOCKS, SCAN_THREADS>>>(
        emissions, transitions, start_tr, end_tr, (float*)d_out);
}